// round 16
// baseline (speedup 1.0000x reference)
#include <cuda_runtime.h>
#include <cuda_fp16.h>
#include <math.h>
#include <stdint.h>

#define NTOK 8192
#define DM 1024
#define DF 4096
#define NE 8
#define BM 128
#define BN 128
#define BK 64
#define MAXROWS (NTOK*2 + NE*BM)   /* 17408 */
#define MT (MAXROWS/BM)            /* 136 */

// smem stage: A 16K + B 16K = 32KB; 3 stages -> 99KB total -> 2 CTAs/SM
// (R14 proved: occ=3 spills accumulators; occ=2 @ 128 regs is the optimum)
#define A_OFF 0
#define B_OFF 16384
#define ST_SIZE 32768
#define NSTAGE 3
#define SMEM_BYTES (1024 + NSTAGE*ST_SIZE)   /* 99328 */

// ---------------- scratch (device globals: allocation-free) ----------------
__device__ __align__(16) __half g_xq[(size_t)MAXROWS * DM];
__device__ __align__(16) __half g_hq[(size_t)MAXROWS * DF];
__device__ __align__(16) __half g_w1h[(size_t)NE * DF * DM];
__device__ __align__(16) __half g_w2h[(size_t)NE * DM * DF];
__device__ int   g_atok[MAXROWS];
__device__ float g_aw[MAXROWS];
__device__ int   g_t2e[NTOK * 2];
__device__ float g_t2w[NTOK * 2];
__device__ int   g_cnt[NE];
__device__ int   g_fill[NE];
__device__ int   g_off[NE + 1];

// ---------------- helpers ----------------
__device__ __forceinline__ uint32_t smem_u32(const void* p) {
    uint32_t a;
    asm("{ .reg .u64 t; cvta.to.shared.u64 t, %1; cvt.u32.u64 %0, t; }" : "=r"(a) : "l"(p));
    return a;
}
#define SWZ(x) ((uint32_t)(x) ^ ((((uint32_t)(x)) >> 3) & 0x70))

__device__ __forceinline__ void cp16(uint32_t dst, const void* src) {
    asm volatile("cp.async.cg.shared.global [%0], [%1], 16;" :: "r"(dst), "l"(src));
}
#define CP_COMMIT() asm volatile("cp.async.commit_group;" ::: "memory")
#define CP_WAITN()  asm volatile("cp.async.wait_group %0;" :: "n"(NSTAGE - 2) : "memory")
#define CP_WAIT0()  asm volatile("cp.async.wait_group 0;" ::: "memory")

__device__ __forceinline__ void ldm4(uint32_t* r, uint32_t addr) {
    asm volatile("ldmatrix.sync.aligned.m8n8.x4.shared.b16 {%0,%1,%2,%3}, [%4];"
        : "=r"(r[0]), "=r"(r[1]), "=r"(r[2]), "=r"(r[3]) : "r"(addr));
}
__device__ __forceinline__ void mma16816(float* c, const uint32_t* a, uint32_t b0, uint32_t b1) {
    asm volatile("mma.sync.aligned.m16n8k16.row.col.f32.f16.f16.f32 "
        "{%0,%1,%2,%3}, {%4,%5,%6,%7}, {%8,%9}, {%0,%1,%2,%3};"
        : "+f"(c[0]), "+f"(c[1]), "+f"(c[2]), "+f"(c[3])
        : "r"(a[0]), "r"(a[1]), "r"(a[2]), "r"(a[3]), "r"(b0), "r"(b1));
}

// ---------------- init ----------------
__global__ void k_init_cnt() {
    int i = threadIdx.x;
    if (i < NE) { g_cnt[i] = 0; g_fill[i] = 0; }
}

__global__ void k_init_slots() {
    int i = blockIdx.x * blockDim.x + threadIdx.x;
    if (i < MAXROWS) g_atok[i] = -1;
}

__global__ void k_zero(float* __restrict__ out) {
    ((float4*)out)[blockIdx.x * 256 + threadIdx.x] = make_float4(0.f, 0.f, 0.f, 0.f);
}

// ---------------- gating ----------------
__global__ __launch_bounds__(256) void k_gate(const float* __restrict__ x,
                                              const float* __restrict__ gw,
                                              const float* __restrict__ gb) {
    __shared__ float sgw[DM * NE];
    int tid = threadIdx.x;
    for (int i = tid; i < DM * NE; i += 256) sgw[i] = gw[i];
    __syncthreads();
    int warp = tid >> 5, lane = tid & 31;
    int t = blockIdx.x * 8 + warp;
    const float* xr = x + (size_t)t * DM;
    float acc[NE];
#pragma unroll
    for (int e = 0; e < NE; e++) acc[e] = 0.f;
    for (int d = lane; d < DM; d += 32) {
        float xv = xr[d];
#pragma unroll
        for (int e = 0; e < NE; e++) acc[e] = fmaf(xv, sgw[d * NE + e], acc[e]);
    }
#pragma unroll
    for (int off = 16; off; off >>= 1)
#pragma unroll
        for (int e = 0; e < NE; e++) acc[e] += __shfl_xor_sync(0xFFFFFFFFu, acc[e], off);
    if (lane == 0) {
        float lg[NE], m = -1e30f;
#pragma unroll
        for (int e = 0; e < NE; e++) { lg[e] = acc[e] + gb[e]; m = fmaxf(m, lg[e]); }
        float ex[NE], s = 0.f;
#pragma unroll
        for (int e = 0; e < NE; e++) { ex[e] = expf(lg[e] - m); s += ex[e]; }
        int e0 = 0;
#pragma unroll
        for (int e = 1; e < NE; e++) if (ex[e] > ex[e0]) e0 = e;
        int e1 = (e0 == 0) ? 1 : 0;
#pragma unroll
        for (int e = 0; e < NE; e++) if (e != e0 && ex[e] > ex[e1]) e1 = e;
        float inv = 1.f / s;
        g_t2e[2 * t] = e0;     g_t2w[2 * t] = ex[e0] * inv;
        g_t2e[2 * t + 1] = e1; g_t2w[2 * t + 1] = ex[e1] * inv;
        atomicAdd(&g_cnt[e0], 1);
        atomicAdd(&g_cnt[e1], 1);
    }
}

__global__ void k_off() {
    g_off[0] = 0;
    for (int e = 0; e < NE; e++)
        g_off[e + 1] = g_off[e] + (((g_cnt[e] + BM - 1) / BM) * BM);
}

__global__ void k_scatter() {
    int t = blockIdx.x * blockDim.x + threadIdx.x;
    if (t >= NTOK) return;
#pragma unroll
    for (int r = 0; r < 2; r++) {
        int e = g_t2e[2 * t + r];
        int p = atomicAdd(&g_fill[e], 1);
        int s = g_off[e] + p;
        g_atok[s] = t;
        g_aw[s] = g_t2w[2 * t + r];
    }
}

// ---------------- gather + fp16 activations ----------------
__global__ __launch_bounds__(256) void k_actsplit(const float* __restrict__ x) {
    int slot = blockIdx.x;
    int tok = g_atok[slot];
    int t4 = threadIdx.x;
    float4 v = make_float4(0.f, 0.f, 0.f, 0.f);
    if (tok >= 0) v = ((const float4*)(x + (size_t)tok * DM))[t4];
    __half2 p0; p0.x = __float2half_rn(v.x); p0.y = __float2half_rn(v.y);
    __half2 p1; p1.x = __float2half_rn(v.z); p1.y = __float2half_rn(v.w);
    size_t base = (size_t)slot * DM + t4 * 4;
    *(__half2*)(g_xq + base)     = p0;
    *(__half2*)(g_xq + base + 2) = p1;
}

// ---------------- transpose + fp16 weights ----------------
// src [e][K][N] (N contiguous) -> dst global [e][N][K] (K contiguous).
// Output referenced as device global INSIDE device code (round-3 lesson).
template <int K, int N, bool IS_W1>
__global__ __launch_bounds__(256) void k_wsplit_t(const float* __restrict__ w) {
    __shared__ float tile[32][33];
    int e = blockIdx.z;
    int n0 = blockIdx.x * 32, k0 = blockIdx.y * 32;
    int tx = threadIdx.x, ty = threadIdx.y;
    const float* we = w + (size_t)e * K * N;
    for (int i = ty; i < 32; i += 8)
        tile[i][tx] = we[(size_t)(k0 + i) * N + n0 + tx];
    __syncthreads();
    __half* ohe = (IS_W1 ? g_w1h : g_w2h) + (size_t)e * N * K;
    for (int i = ty; i < 32; i += 8)
        ohe[(size_t)(n0 + i) * K + k0 + tx] = __float2half_rn(tile[tx][i]);
}

// ================= HMMA mainloop: single fp16 pass, 3-stage, 2 CTAs/SM =================
struct Acc { float v[4][4][4]; };   // [mi][ni][frag]

__device__ __forceinline__ void hmma_mainloop(
    uint32_t sb, Acc& A,
    const __half* Ap, int astride,
    const __half* Bp, int bstride,
    int NC, int tid)
{
    int wid = tid >> 5, L = tid & 31;
    int wm = wid & 1, wn = wid >> 1;   // 2 x 4 warp grid, warp tile 64x32

    int fr = tid & 127;                // fill row
    int hb = (tid >> 7) * 64;          // byte half within 128B row

    auto fill = [&](int s, int c) {
        uint32_t st = sb + s * ST_SIZE;
        const char* pa = (const char*)(Ap + (size_t)fr * astride + c * BK) + hb;
        const char* pb = (const char*)(Bp + (size_t)fr * bstride + c * BK) + hb;
        uint32_t rb = fr * 128 + hb;
#pragma unroll
        for (int j = 0; j < 4; j++) {
            uint32_t o = SWZ(rb + j * 16);
            cp16(st + A_OFF + o, pa + j * 16);
            cp16(st + B_OFF + o, pb + j * 16);
        }
    };

#pragma unroll
    for (int p = 0; p < NSTAGE - 1; p++) { fill(p, p); CP_COMMIT(); }

    int lrow = L & 15;
    int lkb = (L >> 4) * 16;

    for (int c = 0; c < NC; c++) {
        if (c + NSTAGE - 1 < NC) CP_WAITN(); else CP_WAIT0();
        __syncthreads();
        if (c + NSTAGE - 1 < NC) { fill((c + NSTAGE - 1) % NSTAGE, c + NSTAGE - 1); CP_COMMIT(); }
        uint32_t st = sb + (c % NSTAGE) * ST_SIZE;

#pragma unroll
        for (int ks = 0; ks < 4; ks++) {
            uint32_t kb = ks * 32 + lkb;
            uint32_t ah[4][4], bh[2][4];
#pragma unroll
            for (int mi = 0; mi < 4; mi++) {
                uint32_t ro = (wm * 64 + mi * 16 + lrow) * 128 + kb;
                ldm4(ah[mi], st + A_OFF + SWZ(ro));
            }
#pragma unroll
            for (int nj = 0; nj < 2; nj++) {
                uint32_t ro = (wn * 32 + nj * 16 + lrow) * 128 + kb;
                ldm4(bh[nj], st + B_OFF + SWZ(ro));
            }
#pragma unroll
            for (int mi = 0; mi < 4; mi++)
#pragma unroll
                for (int ni = 0; ni < 4; ni++) {
                    int nj = ni >> 1, hf = ni & 1;
                    mma16816(A.v[mi][ni], ah[mi], bh[nj][hf], bh[nj][hf + 2]);
                }
        }
    }
}

// ---------------- GEMM1: h = relu(x @ w1 + b1) -> fp16 ----------------
__global__ __launch_bounds__(256, 2) void k_fmma1(const float* __restrict__ b1) {
    extern __shared__ char smem[];
    int row0 = blockIdx.y * BM;
    if (row0 >= g_off[NE]) return;
    int e = 0;
#pragma unroll
    for (int i = 0; i < NE - 1; i++) if (g_off[i + 1] <= row0) e = i + 1;
    int col0 = blockIdx.x * BN;
    uint32_t sb = (smem_u32(smem) + 1023) & ~1023u;
    int tid = threadIdx.x;

    Acc A;
#pragma unroll
    for (int i = 0; i < 4; i++)
#pragma unroll
        for (int j = 0; j < 4; j++)
#pragma unroll
            for (int k = 0; k < 4; k++) A.v[i][j][k] = 0.f;

    hmma_mainloop(sb, A,
                  g_xq + (size_t)row0 * DM, DM,
                  g_w1h + (size_t)e * DF * DM + (size_t)col0 * DM, DM,
                  DM / BK, tid);

    int wid = tid >> 5, L = tid & 31;
    int wm = wid & 1, wn = wid >> 1;
    const float* b1e = b1 + (size_t)e * DF;
#pragma unroll
    for (int mi = 0; mi < 4; mi++) {
        int r0 = row0 + wm * 64 + mi * 16 + (L >> 2);
#pragma unroll
        for (int ni = 0; ni < 4; ni++) {
            int col = col0 + wn * 32 + ni * 8 + (L & 3) * 2;
            float bb0 = b1e[col], bb1 = b1e[col + 1];
            float* a = A.v[mi][ni];
#pragma unroll
            for (int hrow = 0; hrow < 2; hrow++) {
                int row = r0 + hrow * 8;
                __half2 hp;
                hp.x = __float2half_rn(fmaxf(a[hrow * 2 + 0] + bb0, 0.f));
                hp.y = __float2half_rn(fmaxf(a[hrow * 2 + 1] + bb1, 0.f));
                *(__half2*)(g_hq + (size_t)row * DF + col) = hp;
            }
        }
    }
}

// ---------------- GEMM2: out[tok] += (h @ w2 + b2) * gate (fused combine) ----------------
__global__ __launch_bounds__(256, 2) void k_fmma2(const float* __restrict__ b2,
                                                  float* __restrict__ out) {
    extern __shared__ char smem[];
    int row0 = blockIdx.y * BM;
    if (row0 >= g_off[NE]) return;
    int e = 0;
#pragma unroll
    for (int i = 0; i < NE - 1; i++) if (g_off[i + 1] <= row0) e = i + 1;
    int col0 = blockIdx.x * BN;
    uint32_t sb = (smem_u32(smem) + 1023) & ~1023u;
    int tid = threadIdx.x;

    Acc A;
#pragma unroll
    for (int i = 0; i < 4; i++)
#pragma unroll
        for (int j = 0; j < 4; j++)
#pragma unroll
            for (int k = 0; k < 4; k++) A.v[i][j][k] = 0.f;

    hmma_mainloop(sb, A,
                  g_hq + (size_t)row0 * DF, DF,
                  g_w2h + (size_t)e * DM * DF + (size_t)col0 * DF, DF,
                  DF / BK, tid);

    int wid = tid >> 5, L = tid & 31;
    int wm = wid & 1, wn = wid >> 1;
    const float* b2e = b2 + (size_t)e * DM;
#pragma unroll
    for (int mi = 0; mi < 4; mi++) {
        int r0 = row0 + wm * 64 + mi * 16 + (L >> 2);
#pragma unroll
        for (int ni = 0; ni < 4; ni++) {
            int col = col0 + wn * 32 + ni * 8 + (L & 3) * 2;
            float bb0 = b2e[col], bb1 = b2e[col + 1];
            float* a = A.v[mi][ni];
#pragma unroll
            for (int hrow = 0; hrow < 2; hrow++) {
                int row = r0 + hrow * 8;
                int tok = g_atok[row];
                if (tok >= 0) {
                    float sc = g_aw[row];
                    float* o = out + (size_t)tok * DM + col;
                    atomicAdd(o,     (a[hrow * 2 + 0] + bb0) * sc);
                    atomicAdd(o + 1, (a[hrow * 2 + 1] + bb1) * sc);
                }
            }
        }
    }
}

// ---------------- launch ----------------
extern "C" void kernel_launch(void* const* d_in, const int* in_sizes, int n_in,
                              void* d_out, int out_size) {
    const float* x  = (const float*)d_in[0];
    const float* gw = (const float*)d_in[1];
    const float* gb = (const float*)d_in[2];
    const float* w1 = (const float*)d_in[3];
    const float* b1 = (const float*)d_in[4];
    const float* w2 = (const float*)d_in[5];
    const float* b2 = (const float*)d_in[6];
    float* out = (float*)d_out;

    // statics created on the FIRST (uncaptured) correctness call; reused during capture.
    static cudaStream_t sB = 0;
    static cudaEvent_t evF = 0, evI = 0, evJ1 = 0, evJ2 = 0;
    static bool inited = false;
    if (!inited) {
        cudaStreamCreateWithFlags(&sB, cudaStreamNonBlocking);
        cudaEventCreateWithFlags(&evF, cudaEventDisableTiming);
        cudaEventCreateWithFlags(&evI, cudaEventDisableTiming);
        cudaEventCreateWithFlags(&evJ1, cudaEventDisableTiming);
        cudaEventCreateWithFlags(&evJ2, cudaEventDisableTiming);
        cudaFuncSetAttribute(k_fmma1, cudaFuncAttributeMaxDynamicSharedMemorySize, SMEM_BYTES);
        cudaFuncSetAttribute(k_fmma2, cudaFuncAttributeMaxDynamicSharedMemorySize, SMEM_BYTES);
        inited = true;
    }

    // ---- fork (side stream): slots -> w1 convert -> [evJ1] -> zero + w2 convert ----
    cudaEventRecord(evF, 0);
    cudaStreamWaitEvent(sB, evF, 0);
    k_init_slots<<<(MAXROWS + 255) / 256, 256, 0, sB>>>();
    cudaEventRecord(evI, sB);                      // slots ready (needed before k_scatter)
    k_wsplit_t<DM, DF, true><<<dim3(DF / 32, DM / 32, NE), dim3(32, 8), 0, sB>>>(w1);
    cudaEventRecord(evJ1, sB);                     // w1 ready (all GEMM1 needs)
    k_zero<<<NTOK * DM / 1024, 256, 0, sB>>>(out);
    k_wsplit_t<DF, DM, false><<<dim3(DM / 32, DF / 32, NE), dim3(32, 8), 0, sB>>>(w2);
    cudaEventRecord(evJ2, sB);                     // out zeroed + w2 ready (GEMM2 needs)

    // ---- main chain: gating / routing / activation gather ----
    k_init_cnt<<<1, 32>>>();
    k_gate<<<NTOK / 8, 256>>>(x, gw, gb);
    k_off<<<1, 1>>>();
    cudaStreamWaitEvent(0, evI, 0);               // slot map ready
    k_scatter<<<(NTOK + 255) / 256, 256>>>();
    k_actsplit<<<MAXROWS, 256>>>(x);

    // ---- GEMM1 needs only w1; w2 convert + zero hide under GEMM1 ----
    cudaStreamWaitEvent(0, evJ1, 0);
    k_fmma1<<<dim3(DF / BN, MT), 256, SMEM_BYTES>>>(b1);
    cudaStreamWaitEvent(0, evJ2, 0);
    k_fmma2<<<dim3(DM / BN, MT), 256, SMEM_BYTES>>>(b2, out);
}

// round 17
// speedup vs baseline: 1.0498x; 1.0498x over previous
#include <cuda_runtime.h>
#include <cuda_fp16.h>
#include <math.h>
#include <stdint.h>

#define NTOK 8192
#define DM 1024
#define DF 4096
#define NE 8
#define BM 128
#define BN 128
#define BK 64
#define MAXROWS (NTOK*2 + NE*BM)   /* 17408 */
#define MT (MAXROWS/BM)            /* 136 */

// smem stage: A 16K + B 16K = 32KB; 3 stages -> 99KB total -> 2 CTAs/SM
// (R14 proved: occ=3 spills accumulators; occ=2 @ 128 regs is the optimum)
#define A_OFF 0
#define B_OFF 16384
#define ST_SIZE 32768
#define NSTAGE 3
#define SMEM_BYTES (1024 + NSTAGE*ST_SIZE)   /* 99328 */

// ---------------- scratch (device globals: allocation-free) ----------------
__device__ __align__(16) __half g_xq[(size_t)MAXROWS * DM];
__device__ __align__(16) __half g_hq[(size_t)MAXROWS * DF];
__device__ __align__(16) __half g_w1h[(size_t)NE * DF * DM];
__device__ __align__(16) __half g_w2h[(size_t)NE * DM * DF];
__device__ int   g_atok[MAXROWS];
__device__ float g_aw[MAXROWS];
__device__ int   g_t2e[NTOK * 2];
__device__ float g_t2w[NTOK * 2];
__device__ int   g_cnt[NE];
__device__ int   g_fill[NE];
__device__ int   g_off[NE + 1];

// ---------------- helpers ----------------
__device__ __forceinline__ uint32_t smem_u32(const void* p) {
    uint32_t a;
    asm("{ .reg .u64 t; cvta.to.shared.u64 t, %1; cvt.u32.u64 %0, t; }" : "=r"(a) : "l"(p));
    return a;
}
#define SWZ(x) ((uint32_t)(x) ^ ((((uint32_t)(x)) >> 3) & 0x70))

__device__ __forceinline__ void cp16(uint32_t dst, const void* src) {
    asm volatile("cp.async.cg.shared.global [%0], [%1], 16;" :: "r"(dst), "l"(src));
}
#define CP_COMMIT() asm volatile("cp.async.commit_group;" ::: "memory")
#define CP_WAITN()  asm volatile("cp.async.wait_group %0;" :: "n"(NSTAGE - 2) : "memory")
#define CP_WAIT0()  asm volatile("cp.async.wait_group 0;" ::: "memory")

__device__ __forceinline__ void ldm4(uint32_t* r, uint32_t addr) {
    asm volatile("ldmatrix.sync.aligned.m8n8.x4.shared.b16 {%0,%1,%2,%3}, [%4];"
        : "=r"(r[0]), "=r"(r[1]), "=r"(r[2]), "=r"(r[3]) : "r"(addr));
}
__device__ __forceinline__ void mma16816(float* c, const uint32_t* a, uint32_t b0, uint32_t b1) {
    asm volatile("mma.sync.aligned.m16n8k16.row.col.f32.f16.f16.f32 "
        "{%0,%1,%2,%3}, {%4,%5,%6,%7}, {%8,%9}, {%0,%1,%2,%3};"
        : "+f"(c[0]), "+f"(c[1]), "+f"(c[2]), "+f"(c[3])
        : "r"(a[0]), "r"(a[1]), "r"(a[2]), "r"(a[3]), "r"(b0), "r"(b1));
}

// ---------------- init ----------------
__global__ void k_init_cnt() {
    int i = threadIdx.x;
    if (i < NE) { g_cnt[i] = 0; g_fill[i] = 0; }
}

__global__ void k_init_slots() {
    int i = blockIdx.x * blockDim.x + threadIdx.x;
    if (i < MAXROWS) g_atok[i] = -1;
}

__global__ void k_zero(float* __restrict__ out) {
    ((float4*)out)[blockIdx.x * 256 + threadIdx.x] = make_float4(0.f, 0.f, 0.f, 0.f);
}

// ---------------- gating ----------------
__global__ __launch_bounds__(256) void k_gate(const float* __restrict__ x,
                                              const float* __restrict__ gw,
                                              const float* __restrict__ gb) {
    __shared__ float sgw[DM * NE];
    int tid = threadIdx.x;
    for (int i = tid; i < DM * NE; i += 256) sgw[i] = gw[i];
    __syncthreads();
    int warp = tid >> 5, lane = tid & 31;
    int t = blockIdx.x * 8 + warp;
    const float* xr = x + (size_t)t * DM;
    float acc[NE];
#pragma unroll
    for (int e = 0; e < NE; e++) acc[e] = 0.f;
    for (int d = lane; d < DM; d += 32) {
        float xv = xr[d];
#pragma unroll
        for (int e = 0; e < NE; e++) acc[e] = fmaf(xv, sgw[d * NE + e], acc[e]);
    }
#pragma unroll
    for (int off = 16; off; off >>= 1)
#pragma unroll
        for (int e = 0; e < NE; e++) acc[e] += __shfl_xor_sync(0xFFFFFFFFu, acc[e], off);
    if (lane == 0) {
        float lg[NE], m = -1e30f;
#pragma unroll
        for (int e = 0; e < NE; e++) { lg[e] = acc[e] + gb[e]; m = fmaxf(m, lg[e]); }
        float ex[NE], s = 0.f;
#pragma unroll
        for (int e = 0; e < NE; e++) { ex[e] = expf(lg[e] - m); s += ex[e]; }
        int e0 = 0;
#pragma unroll
        for (int e = 1; e < NE; e++) if (ex[e] > ex[e0]) e0 = e;
        int e1 = (e0 == 0) ? 1 : 0;
#pragma unroll
        for (int e = 0; e < NE; e++) if (e != e0 && ex[e] > ex[e1]) e1 = e;
        float inv = 1.f / s;
        g_t2e[2 * t] = e0;     g_t2w[2 * t] = ex[e0] * inv;
        g_t2e[2 * t + 1] = e1; g_t2w[2 * t + 1] = ex[e1] * inv;
        atomicAdd(&g_cnt[e0], 1);
        atomicAdd(&g_cnt[e1], 1);
    }
}

__global__ void k_off() {
    g_off[0] = 0;
    for (int e = 0; e < NE; e++)
        g_off[e + 1] = g_off[e] + (((g_cnt[e] + BM - 1) / BM) * BM);
}

__global__ void k_scatter() {
    int t = blockIdx.x * blockDim.x + threadIdx.x;
    if (t >= NTOK) return;
#pragma unroll
    for (int r = 0; r < 2; r++) {
        int e = g_t2e[2 * t + r];
        int p = atomicAdd(&g_fill[e], 1);
        int s = g_off[e] + p;
        g_atok[s] = t;
        g_aw[s] = g_t2w[2 * t + r];
    }
}

// ---------------- gather + fp16 activations ----------------
__global__ __launch_bounds__(256) void k_actsplit(const float* __restrict__ x) {
    int slot = blockIdx.x;
    int tok = g_atok[slot];
    int t4 = threadIdx.x;
    float4 v = make_float4(0.f, 0.f, 0.f, 0.f);
    if (tok >= 0) v = ((const float4*)(x + (size_t)tok * DM))[t4];
    __half2 p0; p0.x = __float2half_rn(v.x); p0.y = __float2half_rn(v.y);
    __half2 p1; p1.x = __float2half_rn(v.z); p1.y = __float2half_rn(v.w);
    size_t base = (size_t)slot * DM + t4 * 4;
    *(__half2*)(g_xq + base)     = p0;
    *(__half2*)(g_xq + base + 2) = p1;
}

// ---------------- transpose + fp16 weights (vectorized) ----------------
// src [e][K][N] (N contiguous) -> dst global [e][N][K] (K contiguous).
// Tile 64(K) x 32(N): coalesced 128B row loads, __half2 coalesced stores.
// Output referenced as device global INSIDE device code (round-3 lesson).
template <int K, int N, bool IS_W1>
__global__ __launch_bounds__(256) void k_wsplit_t(const float* __restrict__ w) {
    __shared__ float tile[64][33];
    int e = blockIdx.z;
    int n0 = blockIdx.x * 32, k0 = blockIdx.y * 64;
    int tid = threadIdx.x;
    const float* we = w + (size_t)e * K * N;

    int ln = tid & 31, lk = tid >> 5;          // load: 32 n-cols x 8 k-rows/thread
#pragma unroll
    for (int i = 0; i < 8; i++)
        tile[lk + i * 8][ln] = we[(size_t)(k0 + lk + i * 8) * N + n0 + ln];
    __syncthreads();

    __half* ohe = (IS_W1 ? g_w1h : g_w2h) + (size_t)e * N * K;
    int sn = tid >> 3, sk = (tid & 7) * 8;     // store: each thread 8 K-vals of one n-row
    __half2* orow = (__half2*)(ohe + (size_t)(n0 + sn) * K + k0 + sk);
#pragma unroll
    for (int i = 0; i < 4; i++) {
        __half2 hv;
        hv.x = __float2half_rn(tile[sk + 2 * i][sn]);
        hv.y = __float2half_rn(tile[sk + 2 * i + 1][sn]);
        orow[i] = hv;
    }
}

// ================= HMMA mainloop: single fp16 pass, 3-stage, 2 CTAs/SM =================
struct Acc { float v[4][4][4]; };   // [mi][ni][frag]

__device__ __forceinline__ void hmma_mainloop(
    uint32_t sb, Acc& A,
    const __half* Ap, int astride,
    const __half* Bp, int bstride,
    int NC, int tid)
{
    int wid = tid >> 5, L = tid & 31;
    int wm = wid & 1, wn = wid >> 1;   // 2 x 4 warp grid, warp tile 64x32

    int fr = tid & 127;                // fill row
    int hb = (tid >> 7) * 64;          // byte half within 128B row

    auto fill = [&](int s, int c) {
        uint32_t st = sb + s * ST_SIZE;
        const char* pa = (const char*)(Ap + (size_t)fr * astride + c * BK) + hb;
        const char* pb = (const char*)(Bp + (size_t)fr * bstride + c * BK) + hb;
        uint32_t rb = fr * 128 + hb;
#pragma unroll
        for (int j = 0; j < 4; j++) {
            uint32_t o = SWZ(rb + j * 16);
            cp16(st + A_OFF + o, pa + j * 16);
            cp16(st + B_OFF + o, pb + j * 16);
        }
    };

#pragma unroll
    for (int p = 0; p < NSTAGE - 1; p++) { fill(p, p); CP_COMMIT(); }

    int lrow = L & 15;
    int lkb = (L >> 4) * 16;

    for (int c = 0; c < NC; c++) {
        if (c + NSTAGE - 1 < NC) CP_WAITN(); else CP_WAIT0();
        __syncthreads();
        if (c + NSTAGE - 1 < NC) { fill((c + NSTAGE - 1) % NSTAGE, c + NSTAGE - 1); CP_COMMIT(); }
        uint32_t st = sb + (c % NSTAGE) * ST_SIZE;

#pragma unroll
        for (int ks = 0; ks < 4; ks++) {
            uint32_t kb = ks * 32 + lkb;
            uint32_t ah[4][4], bh[2][4];
#pragma unroll
            for (int mi = 0; mi < 4; mi++) {
                uint32_t ro = (wm * 64 + mi * 16 + lrow) * 128 + kb;
                ldm4(ah[mi], st + A_OFF + SWZ(ro));
            }
#pragma unroll
            for (int nj = 0; nj < 2; nj++) {
                uint32_t ro = (wn * 32 + nj * 16 + lrow) * 128 + kb;
                ldm4(bh[nj], st + B_OFF + SWZ(ro));
            }
#pragma unroll
            for (int mi = 0; mi < 4; mi++)
#pragma unroll
                for (int ni = 0; ni < 4; ni++) {
                    int nj = ni >> 1, hf = ni & 1;
                    mma16816(A.v[mi][ni], ah[mi], bh[nj][hf], bh[nj][hf + 2]);
                }
        }
    }
}

// ---------------- GEMM1: h = relu(x @ w1 + b1) -> fp16 ----------------
__global__ __launch_bounds__(256, 2) void k_fmma1(const float* __restrict__ b1) {
    extern __shared__ char smem[];
    int row0 = blockIdx.y * BM;
    if (row0 >= g_off[NE]) return;
    int e = 0;
#pragma unroll
    for (int i = 0; i < NE - 1; i++) if (g_off[i + 1] <= row0) e = i + 1;
    int col0 = blockIdx.x * BN;
    uint32_t sb = (smem_u32(smem) + 1023) & ~1023u;
    int tid = threadIdx.x;

    Acc A;
#pragma unroll
    for (int i = 0; i < 4; i++)
#pragma unroll
        for (int j = 0; j < 4; j++)
#pragma unroll
            for (int k = 0; k < 4; k++) A.v[i][j][k] = 0.f;

    hmma_mainloop(sb, A,
                  g_xq + (size_t)row0 * DM, DM,
                  g_w1h + (size_t)e * DF * DM + (size_t)col0 * DM, DM,
                  DM / BK, tid);

    int wid = tid >> 5, L = tid & 31;
    int wm = wid & 1, wn = wid >> 1;
    const float* b1e = b1 + (size_t)e * DF;
#pragma unroll
    for (int mi = 0; mi < 4; mi++) {
        int r0 = row0 + wm * 64 + mi * 16 + (L >> 2);
#pragma unroll
        for (int ni = 0; ni < 4; ni++) {
            int col = col0 + wn * 32 + ni * 8 + (L & 3) * 2;
            float bb0 = b1e[col], bb1 = b1e[col + 1];
            float* a = A.v[mi][ni];
#pragma unroll
            for (int hrow = 0; hrow < 2; hrow++) {
                int row = r0 + hrow * 8;
                __half2 hp;
                hp.x = __float2half_rn(fmaxf(a[hrow * 2 + 0] + bb0, 0.f));
                hp.y = __float2half_rn(fmaxf(a[hrow * 2 + 1] + bb1, 0.f));
                *(__half2*)(g_hq + (size_t)row * DF + col) = hp;
            }
        }
    }
}

// ---------------- GEMM2: out[tok] += (h @ w2 + b2) * gate (fused combine) ----------------
__global__ __launch_bounds__(256, 2) void k_fmma2(const float* __restrict__ b2,
                                                  float* __restrict__ out) {
    extern __shared__ char smem[];
    int row0 = blockIdx.y * BM;
    if (row0 >= g_off[NE]) return;
    int e = 0;
#pragma unroll
    for (int i = 0; i < NE - 1; i++) if (g_off[i + 1] <= row0) e = i + 1;
    int col0 = blockIdx.x * BN;
    uint32_t sb = (smem_u32(smem) + 1023) & ~1023u;
    int tid = threadIdx.x;

    Acc A;
#pragma unroll
    for (int i = 0; i < 4; i++)
#pragma unroll
        for (int j = 0; j < 4; j++)
#pragma unroll
            for (int k = 0; k < 4; k++) A.v[i][j][k] = 0.f;

    hmma_mainloop(sb, A,
                  g_hq + (size_t)row0 * DF, DF,
                  g_w2h + (size_t)e * DM * DF + (size_t)col0 * DF, DF,
                  DF / BK, tid);

    int wid = tid >> 5, L = tid & 31;
    int wm = wid & 1, wn = wid >> 1;
    const float* b2e = b2 + (size_t)e * DM;
#pragma unroll
    for (int mi = 0; mi < 4; mi++) {
        int r0 = row0 + wm * 64 + mi * 16 + (L >> 2);
#pragma unroll
        for (int ni = 0; ni < 4; ni++) {
            int col = col0 + wn * 32 + ni * 8 + (L & 3) * 2;
            float bb0 = b2e[col], bb1 = b2e[col + 1];
            float* a = A.v[mi][ni];
#pragma unroll
            for (int hrow = 0; hrow < 2; hrow++) {
                int row = r0 + hrow * 8;
                int tok = g_atok[row];
                if (tok >= 0) {
                    float sc = g_aw[row];
                    float* o = out + (size_t)tok * DM + col;
                    atomicAdd(o,     (a[hrow * 2 + 0] + bb0) * sc);
                    atomicAdd(o + 1, (a[hrow * 2 + 1] + bb1) * sc);
                }
            }
        }
    }
}

// ---------------- launch ----------------
extern "C" void kernel_launch(void* const* d_in, const int* in_sizes, int n_in,
                              void* d_out, int out_size) {
    const float* x  = (const float*)d_in[0];
    const float* gw = (const float*)d_in[1];
    const float* gb = (const float*)d_in[2];
    const float* w1 = (const float*)d_in[3];
    const float* b1 = (const float*)d_in[4];
    const float* w2 = (const float*)d_in[5];
    const float* b2 = (const float*)d_in[6];
    float* out = (float*)d_out;

    // statics created on the FIRST (uncaptured) correctness call; reused during capture.
    static cudaStream_t sB = 0;
    static cudaEvent_t evF = 0, evI = 0, evJ1 = 0, evJ2 = 0;
    static bool inited = false;
    if (!inited) {
        cudaStreamCreateWithFlags(&sB, cudaStreamNonBlocking);
        cudaEventCreateWithFlags(&evF, cudaEventDisableTiming);
        cudaEventCreateWithFlags(&evI, cudaEventDisableTiming);
        cudaEventCreateWithFlags(&evJ1, cudaEventDisableTiming);
        cudaEventCreateWithFlags(&evJ2, cudaEventDisableTiming);
        cudaFuncSetAttribute(k_fmma1, cudaFuncAttributeMaxDynamicSharedMemorySize, SMEM_BYTES);
        cudaFuncSetAttribute(k_fmma2, cudaFuncAttributeMaxDynamicSharedMemorySize, SMEM_BYTES);
        inited = true;
    }

    // ---- fork (side stream): slots -> w1 convert -> [evJ1] -> zero + w2 convert ----
    cudaEventRecord(evF, 0);
    cudaStreamWaitEvent(sB, evF, 0);
    k_init_slots<<<(MAXROWS + 255) / 256, 256, 0, sB>>>();
    cudaEventRecord(evI, sB);                      // slots ready (needed before k_scatter)
    k_wsplit_t<DM, DF, true><<<dim3(DF / 32, DM / 64, NE), 256, 0, sB>>>(w1);
    cudaEventRecord(evJ1, sB);                     // w1 ready (all GEMM1 needs)
    k_zero<<<NTOK * DM / 1024, 256, 0, sB>>>(out);
    k_wsplit_t<DF, DM, false><<<dim3(DM / 32, DF / 64, NE), 256, 0, sB>>>(w2);
    cudaEventRecord(evJ2, sB);                     // out zeroed + w2 ready (GEMM2 needs)

    // ---- main chain: gating / routing / activation gather ----
    k_init_cnt<<<1, 32>>>();
    k_gate<<<NTOK / 8, 256>>>(x, gw, gb);
    k_off<<<1, 1>>>();
    cudaStreamWaitEvent(0, evI, 0);               // slot map ready
    k_scatter<<<(NTOK + 255) / 256, 256>>>();
    k_actsplit<<<MAXROWS, 256>>>(x);

    // ---- GEMM1 needs only w1; w2 convert + zero hide under GEMM1 ----
    cudaStreamWaitEvent(0, evJ1, 0);
    k_fmma1<<<dim3(DF / BN, MT), 256, SMEM_BYTES>>>(b1);
    cudaStreamWaitEvent(0, evJ2, 0);
    k_fmma2<<<dim3(DM / BN, MT), 256, SMEM_BYTES>>>(b2, out);
}